// round 2
// baseline (speedup 1.0000x reference)
#include <cuda_runtime.h>
#include <cuda_bf16.h>
#include <math.h>

// Problem constants
#define BATCH 2048
#define FEAT 256
#define TREES 256
#define DEPTH 6
#define NCOLS (TREES * DEPTH)   // 1536
#define LEAVES 64
#define NNZ_MAX 128             // capacity; expected support ~23

// Scratch (device globals: no allocation allowed)
__device__ float2 g_pairs[NCOLS * NNZ_MAX];   // {weight, idx-as-float-bits}
__device__ int    g_cnt[NCOLS];

// ---------------------------------------------------------------------------
// Kernel 1: exact sparsemax per (tree, depth) column + compaction to sparse
// lists. 1536 blocks x 256 threads. Column f-stride is 1536 floats.
// ---------------------------------------------------------------------------
__global__ __launch_bounds__(256) void k_sparsemax(const float* __restrict__ logits) {
    __shared__ float s[FEAT];
    __shared__ float wmax[8];
    __shared__ int   wcnt[8];

    const int col = blockIdx.x;
    const int tid = threadIdx.x;
    const int ln  = tid & 31;
    const int wd  = tid >> 5;

    const float v = logits[tid * NCOLS + col];

    // ---- block max ----
    float m = v;
    #pragma unroll
    for (int o = 16; o; o >>= 1) m = fmaxf(m, __shfl_xor_sync(0xffffffffu, m, o));
    if (ln == 0) wmax[wd] = m;
    __syncthreads();
    float mx = wmax[0];
    #pragma unroll
    for (int i = 1; i < 8; i++) mx = fmaxf(mx, wmax[i]);

    const float xsv = v - mx;
    s[tid] = xsv;
    __syncthreads();

    // ---- bitonic sort, DESCENDING ----
    #pragma unroll 1
    for (int k = 2; k <= FEAT; k <<= 1) {
        #pragma unroll 1
        for (int j = k >> 1; j > 0; j >>= 1) {
            int ixj = tid ^ j;
            if (ixj > tid) {
                float a = s[tid], b = s[ixj];
                bool descBlock = ((tid & k) == 0);
                bool doSwap = descBlock ? (a < b) : (a > b);
                if (doSwap) { s[tid] = b; s[ixj] = a; }
            }
            __syncthreads();
        }
    }

    const float z = s[tid];   // sorted (descending) value at rank tid
    // ---- inclusive scan (Hillis-Steele) over sorted values ----
    #pragma unroll 1
    for (int off = 1; off < FEAT; off <<= 1) {
        float add = (tid >= off) ? s[tid - off] : 0.0f;
        __syncthreads();
        s[tid] += add;
        __syncthreads();
    }

    const float cs = s[tid] - 1.0f;
    const bool cond = ((float)(tid + 1) * z > cs);
    const int k = __syncthreads_count(cond);        // support size (>=1 always)

    const float tau = (s[k - 1] - 1.0f) / (float)k;
    const float w = fmaxf(xsv - tau, 0.0f);

    // ---- compaction ----
    const bool nz = (w > 0.0f);
    unsigned bal = __ballot_sync(0xffffffffu, nz);
    if (ln == 0) wcnt[wd] = __popc(bal);
    __syncthreads();
    int base = 0;
    #pragma unroll
    for (int i = 0; i < 8; i++) { if (i < wd) base += wcnt[i]; }
    int pos = base + __popc(bal & ((1u << ln) - 1u));
    if (nz && pos < NNZ_MAX) {
        g_pairs[col * NNZ_MAX + pos] = make_float2(w, __int_as_float(tid));
    }
    if (tid == 0) {
        int tot = 0;
        #pragma unroll
        for (int i = 0; i < 8; i++) tot += wcnt[i];
        g_cnt[col] = tot < NNZ_MAX ? tot : NNZ_MAX;
    }
}

// ---------------------------------------------------------------------------
// Kernel 2: fused sparse contraction + tree evaluation.
// Block: 256 threads = 8 warps. Tile: 32 batch rows x 32 trees.
// Lane = batch row (so sparse-entry loads are warp-uniform, x-gathers are
// bank-conflict-free with pitch 33). Each warp handles 4 trees.
// ---------------------------------------------------------------------------
__global__ __launch_bounds__(256) void k_forest(
    const float* __restrict__ x,
    const float* __restrict__ response,
    const float* __restrict__ thresholds,
    const float* __restrict__ logtemp,
    float* __restrict__ out)
{
    __shared__ float xs[FEAT * 33];     // [f][b], pitch 33 -> conflict-free both ways
    __shared__ float outs[32 * 33];     // [tree_local][b]

    const int tid  = threadIdx.x;
    const int lane = tid & 31;
    const int warp = tid >> 5;
    const int b0 = blockIdx.x * 32;
    const int t0 = blockIdx.y * 32;

    // load x tile transposed: read coalesced, write stride-33 (conflict-free)
    #pragma unroll 4
    for (int j = 0; j < 32; j++) {
        xs[tid * 33 + j] = x[(b0 + j) * FEAT + tid];
    }
    __syncthreads();

    const float* xb = xs + lane;        // lane-fixed base

    for (int tt = warp; tt < 32; tt += 8) {
        const int t = t0 + tt;
        float sv[DEPTH];
        #pragma unroll
        for (int dd = 0; dd < DEPTH; dd++) {
            const int col = t * DEPTH + dd;
            const int n = g_cnt[col];
            const float2* __restrict__ p = g_pairs + col * NNZ_MAX;
            float acc = 0.0f;
            #pragma unroll 4
            for (int j = 0; j < n; j++) {
                float2 e = __ldg(&p[j]);                 // warp-uniform
                int idx = __float_as_int(e.y);
                acc = fmaf(e.x, xb[idx * 33], acc);      // conflict-free gather
            }
            float th = __ldg(&thresholds[col]);
            float lt = __ldg(&logtemp[col]);
            float tl = (acc - th) * expf(-lt);
            sv[dd] = __saturatef(0.5f * tl + 0.5f);      // sparsemoid
        }

        // leaf-weight product tree over depths 0..4 (32 partial products)
        float arr[32];
        arr[0] = 1.0f;
        #pragma unroll
        for (int d = 0; d < 5; d++) {
            const float sd = sv[d];
            const float cd = 1.0f - sd;
            #pragma unroll
            for (int i = (1 << d) - 1; i >= 0; i--) {
                float a = arr[i];
                arr[i + (1 << d)] = a * cd;   // bit d = 1 -> factor (1-s)
                arr[i]            = a * sd;   // bit d = 0 -> factor s
            }
        }
        // fold depth 5 into the response dot: leaf c = i (+32 if bit5)
        const float* __restrict__ r = response + t * LEAVES;
        const float s5 = sv[5], c5 = 1.0f - sv[5];
        float o = 0.0f;
        #pragma unroll
        for (int i = 0; i < 32; i++) {
            float u = s5 * __ldg(r + i) + c5 * __ldg(r + 32 + i);
            o = fmaf(arr[i], u, o);
        }
        outs[tt * 33 + lane] = o;
    }
    __syncthreads();

    // coalesced store of the 32x32 output tile
    const int tl = tid & 31;
    const int bl = tid >> 5;
    #pragma unroll
    for (int bb = bl; bb < 32; bb += 8) {
        out[(b0 + bb) * TREES + t0 + tl] = outs[tl * 33 + bb];
    }
}

// ---------------------------------------------------------------------------
extern "C" void kernel_launch(void* const* d_in, const int* in_sizes, int n_in,
                              void* d_out, int out_size)
{
    const float* x    = (const float*)d_in[0];   // [2048, 256]
    const float* resp = (const float*)d_in[1];   // [256, 1, 64]
    const float* fsl  = (const float*)d_in[2];   // [256, 256, 6]
    const float* th   = (const float*)d_in[3];   // [256, 6]
    const float* lt   = (const float*)d_in[4];   // [256, 6]
    float* out        = (float*)d_out;           // [2048, 256]

    k_sparsemax<<<NCOLS, 256>>>(fsl);
    dim3 g2(BATCH / 32, TREES / 32);
    k_forest<<<g2, 256>>>(x, resp, th, lt, out);
}

// round 6
// speedup vs baseline: 1.1143x; 1.1143x over previous
#include <cuda_runtime.h>
#include <cuda_bf16.h>
#include <math.h>

// Problem constants
#define BATCH 2048
#define FEAT 256
#define TREES 256
#define DEPTH 6
#define NCOLS (TREES * DEPTH)   // 1536
#define LEAVES 64
#define NNZ_MAX 128             // capacity; expected support ~23

// Scratch (device globals: no allocation allowed)
__device__ float                       g_w[NCOLS * NNZ_MAX];  // weights, zero-padded to mult of 8
__device__ __align__(16) unsigned char g_i[NCOLS * NNZ_MAX];  // feature indices
__device__ __align__(16) float4        g_meta[NCOLS];         // {threshold, exp(-logtemp), count, 0}

// ---------------------------------------------------------------------------
// Kernel 1: exact sparsemax per (tree, depth) column + compaction to sparse
// lists + per-column metadata packing. 1536 blocks x 256 threads.
// ---------------------------------------------------------------------------
__global__ __launch_bounds__(256) void k_sparsemax(
    const float* __restrict__ logits,
    const float* __restrict__ thresholds,
    const float* __restrict__ logtemp)
{
    __shared__ float s[FEAT];
    __shared__ float wmax[8];
    __shared__ int   wcnt[8];

    const int col = blockIdx.x;
    const int tid = threadIdx.x;
    const int ln  = tid & 31;
    const int wd  = tid >> 5;

    const float v = logits[tid * NCOLS + col];

    // ---- block max ----
    float m = v;
    #pragma unroll
    for (int o = 16; o; o >>= 1) m = fmaxf(m, __shfl_xor_sync(0xffffffffu, m, o));
    if (ln == 0) wmax[wd] = m;
    __syncthreads();
    float mx = wmax[0];
    #pragma unroll
    for (int i = 1; i < 8; i++) mx = fmaxf(mx, wmax[i]);

    const float xsv = v - mx;
    s[tid] = xsv;
    __syncthreads();

    // ---- bitonic sort, DESCENDING ----
    #pragma unroll 1
    for (int k = 2; k <= FEAT; k <<= 1) {
        #pragma unroll 1
        for (int j = k >> 1; j > 0; j >>= 1) {
            int ixj = tid ^ j;
            if (ixj > tid) {
                float a = s[tid], b = s[ixj];
                bool descBlock = ((tid & k) == 0);
                bool doSwap = descBlock ? (a < b) : (a > b);
                if (doSwap) { s[tid] = b; s[ixj] = a; }
            }
            __syncthreads();
        }
    }

    const float z = s[tid];   // sorted (descending) value at rank tid
    // ---- inclusive scan (Hillis-Steele) over sorted values ----
    #pragma unroll 1
    for (int off = 1; off < FEAT; off <<= 1) {
        float add = (tid >= off) ? s[tid - off] : 0.0f;
        __syncthreads();
        s[tid] += add;
        __syncthreads();
    }

    const float cs = s[tid] - 1.0f;
    const bool cond = ((float)(tid + 1) * z > cs);
    const int k = __syncthreads_count(cond);        // support size (>=1 always)

    const float tau = (s[k - 1] - 1.0f) / (float)k;
    const float w = fmaxf(xsv - tau, 0.0f);

    // ---- compaction ----
    const bool nz = (w > 0.0f);
    unsigned bal = __ballot_sync(0xffffffffu, nz);
    if (ln == 0) wcnt[wd] = __popc(bal);
    __syncthreads();
    int base = 0;
    #pragma unroll
    for (int i = 0; i < 8; i++) { if (i < wd) base += wcnt[i]; }
    int pos = base + __popc(bal & ((1u << ln) - 1u));
    if (nz && pos < NNZ_MAX) {
        g_w[col * NNZ_MAX + pos] = w;
        g_i[col * NNZ_MAX + pos] = (unsigned char)tid;
    }

    int tot = 0;
    #pragma unroll
    for (int i = 0; i < 8; i++) tot += wcnt[i];
    if (tot > NNZ_MAX) tot = NNZ_MAX;
    const int nround = (tot + 7) & ~7;              // pad to multiple of 8
    if (tid >= tot && tid < nround) {
        g_w[col * NNZ_MAX + tid] = 0.0f;            // zero-weight padding
        g_i[col * NNZ_MAX + tid] = 0;
    }
    if (tid == 0) {
        const float th = thresholds[col];
        const float sc = expf(-logtemp[col]);
        g_meta[col] = make_float4(th, sc, __int_as_float(nround), 0.0f);
    }
}

// ---------------------------------------------------------------------------
// Kernel 2: fused sparse contraction + tree evaluation.
// Block: 256 threads = 8 warps. Tile: 32 batch rows x 32 trees.
// Lane = batch row (sparse-list loads are warp-uniform; x-gather hits 32
// distinct banks with pitch 33). 4 independent accumulators break the FFMA
// dependency chain; response staged in smem; metadata as one aligned float4
// per column.
// ---------------------------------------------------------------------------
__global__ __launch_bounds__(256) void k_forest(
    const float* __restrict__ x,
    const float* __restrict__ response,
    float* __restrict__ out)
{
    __shared__ float xs[FEAT * 33];     // [f][b], pitch 33 -> conflict-free
    __shared__ float rs[32 * LEAVES];   // response tile, [tree_local][64]
    __shared__ float outs[32 * 33];     // [tree_local][b]

    const int tid  = threadIdx.x;
    const int lane = tid & 31;
    const int warp = tid >> 5;
    const int b0 = blockIdx.x * 32;
    const int t0 = blockIdx.y * 32;

    // load x tile transposed: read coalesced, write stride-33 (conflict-free)
    #pragma unroll 4
    for (int j = 0; j < 32; j++) {
        xs[tid * 33 + j] = x[(b0 + j) * FEAT + tid];
    }
    // stage response tile (contiguous)
    #pragma unroll
    for (int i = tid; i < 32 * LEAVES; i += 256) {
        rs[i] = response[t0 * LEAVES + i];
    }
    __syncthreads();

    const float* xb = xs + lane;        // lane-fixed base

    for (int tt = warp; tt < 32; tt += 8) {
        const int t = t0 + tt;
        const int colb = t * DEPTH;

        // hoisted per-column metadata: one aligned 16B uniform load each
        float4 meta[DEPTH];
        #pragma unroll
        for (int dd = 0; dd < DEPTH; dd++) meta[dd] = __ldg(&g_meta[colb + dd]);

        float sv[DEPTH];
        #pragma unroll
        for (int dd = 0; dd < DEPTH; dd++) {
            const int n = __float_as_int(meta[dd].z);       // multiple of 8
            const float* __restrict__ wp = g_w + (colb + dd) * NNZ_MAX;
            const unsigned char* __restrict__ ip = g_i + (size_t)(colb + dd) * NNZ_MAX;

            float a0 = 0.f, a1 = 0.f, a2 = 0.f, a3 = 0.f;
            #pragma unroll 1
            for (int j = 0; j < n; j += 8) {
                const float4 wA = *(const float4*)(wp + j);
                const float4 wB = *(const float4*)(wp + j + 4);
                const uint2  iv = *(const uint2*)(ip + j);
                const unsigned u0 = iv.x, u1 = iv.y;
                a0 = fmaf(wA.x, xb[( u0        & 255u) * 33], a0);
                a1 = fmaf(wA.y, xb[((u0 >>  8) & 255u) * 33], a1);
                a2 = fmaf(wA.z, xb[((u0 >> 16) & 255u) * 33], a2);
                a3 = fmaf(wA.w, xb[( u0 >> 24        ) * 33], a3);
                a0 = fmaf(wB.x, xb[( u1        & 255u) * 33], a0);
                a1 = fmaf(wB.y, xb[((u1 >>  8) & 255u) * 33], a1);
                a2 = fmaf(wB.z, xb[((u1 >> 16) & 255u) * 33], a2);
                a3 = fmaf(wB.w, xb[( u1 >> 24        ) * 33], a3);
            }
            const float acc = (a0 + a1) + (a2 + a3);

            const float tl = (acc - meta[dd].x) * meta[dd].y;
            sv[dd] = __saturatef(0.5f * tl + 0.5f);      // sparsemoid
        }

        // leaf-weight product tree over depths 0..4 (32 partial products)
        float arr[32];
        arr[0] = 1.0f;
        #pragma unroll
        for (int d = 0; d < 5; d++) {
            const float sd = sv[d];
            const float cd = 1.0f - sd;
            #pragma unroll
            for (int i = (1 << d) - 1; i >= 0; i--) {
                float a = arr[i];
                arr[i + (1 << d)] = a * cd;   // bit d = 1 -> factor (1-s)
                arr[i]            = a * sd;   // bit d = 0 -> factor s
            }
        }
        // fold depth 5 into the response dot (response from smem, broadcast LDS)
        const float* __restrict__ r = rs + tt * LEAVES;
        const float s5 = sv[5], c5 = 1.0f - sv[5];
        float o = 0.0f;
        #pragma unroll
        for (int i = 0; i < 32; i++) {
            o = fmaf(arr[i], fmaf(s5, r[i], c5 * r[32 + i]), o);
        }
        outs[tt * 33 + lane] = o;
    }
    __syncthreads();

    // coalesced store of the 32x32 output tile
    const int tl = tid & 31;
    const int bl = tid >> 5;
    #pragma unroll
    for (int bb = bl; bb < 32; bb += 8) {
        out[(b0 + bb) * TREES + t0 + tl] = outs[tl * 33 + bb];
    }
}

// ---------------------------------------------------------------------------
extern "C" void kernel_launch(void* const* d_in, const int* in_sizes, int n_in,
                              void* d_out, int out_size)
{
    const float* x    = (const float*)d_in[0];   // [2048, 256]
    const float* resp = (const float*)d_in[1];   // [256, 1, 64]
    const float* fsl  = (const float*)d_in[2];   // [256, 256, 6]
    const float* th   = (const float*)d_in[3];   // [256, 6]
    const float* lt   = (const float*)d_in[4];   // [256, 6]
    float* out        = (float*)d_out;           // [2048, 256]

    k_sparsemax<<<NCOLS, 256>>>(fsl, th, lt);
    dim3 g2(BATCH / 32, TREES / 32);
    k_forest<<<g2, 256>>>(x, resp, out);
}

// round 7
// speedup vs baseline: 1.2370x; 1.1101x over previous
#include <cuda_runtime.h>
#include <cuda_bf16.h>
#include <math.h>

// Problem constants
#define BATCH 2048
#define FEAT 256
#define TREES 256
#define DEPTH 6
#define NCOLS (TREES * DEPTH)   // 1536
#define LEAVES 64
#define NNZ_MAX 128             // capacity; expected support ~23

// Scratch (device globals: no allocation allowed)
__device__ float                       g_w[NCOLS * NNZ_MAX];  // weights, zero-padded to mult of 8
__device__ __align__(16) unsigned char g_i[NCOLS * NNZ_MAX];  // feature indices
__device__ __align__(16) float4        g_meta[NCOLS];         // {threshold, exp(-logtemp), count, 0}
__device__ float                       g_logT[NCOLS * FEAT];  // transposed logits [col][f]

// ---------------------------------------------------------------------------
// Kernel 0: transpose logits [F][NCOLS] -> [NCOLS][F] so k_sparsemax reads
// coalesced. Standard 32x32 tile via smem.
// ---------------------------------------------------------------------------
__global__ __launch_bounds__(256) void k_transpose(const float* __restrict__ in) {
    __shared__ float t[32][33];
    const int tx = threadIdx.x;          // 0..31
    const int ty = threadIdx.y;          // 0..7
    const int c0 = blockIdx.x * 32;      // col tile
    const int f0 = blockIdx.y * 32;      // feature tile
    #pragma unroll
    for (int r = 0; r < 32; r += 8)
        t[ty + r][tx] = in[(f0 + ty + r) * NCOLS + c0 + tx];
    __syncthreads();
    #pragma unroll
    for (int r = 0; r < 32; r += 8)
        g_logT[(c0 + ty + r) * FEAT + f0 + tx] = t[tx][ty + r];
}

// ---------------------------------------------------------------------------
// Kernel 1: exact sparsemax per (tree, depth) column + compaction + metadata.
// 1536 blocks x 256 threads. Reads transposed logits (coalesced).
// Scan done with warp shuffles (1 barrier instead of 16).
// ---------------------------------------------------------------------------
__global__ __launch_bounds__(256) void k_sparsemax(
    const float* __restrict__ thresholds,
    const float* __restrict__ logtemp)
{
    __shared__ float s[FEAT];
    __shared__ float wred[8];
    __shared__ int   wcnt[8];

    const int col = blockIdx.x;
    const int tid = threadIdx.x;
    const int ln  = tid & 31;
    const int wd  = tid >> 5;

    const float v = g_logT[col * FEAT + tid];      // coalesced

    // ---- block max ----
    float m = v;
    #pragma unroll
    for (int o = 16; o; o >>= 1) m = fmaxf(m, __shfl_xor_sync(0xffffffffu, m, o));
    if (ln == 0) wred[wd] = m;
    __syncthreads();
    float mx = wred[0];
    #pragma unroll
    for (int i = 1; i < 8; i++) mx = fmaxf(mx, wred[i]);

    const float xsv = v - mx;
    s[tid] = xsv;
    __syncthreads();

    // ---- bitonic sort, DESCENDING ----
    #pragma unroll 1
    for (int k = 2; k <= FEAT; k <<= 1) {
        #pragma unroll 1
        for (int j = k >> 1; j > 0; j >>= 1) {
            int ixj = tid ^ j;
            if (ixj > tid) {
                float a = s[tid], b = s[ixj];
                bool descBlock = ((tid & k) == 0);
                bool doSwap = descBlock ? (a < b) : (a > b);
                if (doSwap) { s[tid] = b; s[ixj] = a; }
            }
            __syncthreads();
        }
    }

    const float z = s[tid];   // sorted (descending) value at rank tid

    // ---- inclusive scan via warp shuffles ----
    float ws = z;
    #pragma unroll
    for (int o = 1; o < 32; o <<= 1) {
        float tmp = __shfl_up_sync(0xffffffffu, ws, o);
        if (ln >= o) ws += tmp;
    }
    if (ln == 31) wred[wd] = ws;
    __syncthreads();
    float pre = 0.0f;
    #pragma unroll
    for (int i = 0; i < 8; i++) { if (i < wd) pre += wred[i]; }
    const float inc = ws + pre;                     // inclusive cumsum of sorted z
    s[tid] = inc;                                   // for s[k-1] lookup below

    const float cs = inc - 1.0f;
    const bool cond = ((float)(tid + 1) * z > cs);
    const int k = __syncthreads_count(cond);        // support size; also a barrier

    const float tau = (s[k - 1] - 1.0f) / (float)k;
    const float w = fmaxf(xsv - tau, 0.0f);

    // ---- compaction ----
    const bool nz = (w > 0.0f);
    unsigned bal = __ballot_sync(0xffffffffu, nz);
    if (ln == 0) wcnt[wd] = __popc(bal);
    __syncthreads();
    int base = 0;
    #pragma unroll
    for (int i = 0; i < 8; i++) { if (i < wd) base += wcnt[i]; }
    int pos = base + __popc(bal & ((1u << ln) - 1u));
    if (nz && pos < NNZ_MAX) {
        g_w[col * NNZ_MAX + pos] = w;
        g_i[col * NNZ_MAX + pos] = (unsigned char)tid;
    }

    int tot = 0;
    #pragma unroll
    for (int i = 0; i < 8; i++) tot += wcnt[i];
    if (tot > NNZ_MAX) tot = NNZ_MAX;
    const int nround = (tot + 7) & ~7;              // pad to multiple of 8
    if (tid >= tot && tid < nround) {
        g_w[col * NNZ_MAX + tid] = 0.0f;            // zero-weight padding
        g_i[col * NNZ_MAX + tid] = 0;
    }
    if (tid == 0) {
        const float th = thresholds[col];
        const float sc = expf(-logtemp[col]);
        g_meta[col] = make_float4(th, sc, __int_as_float(nround), 0.0f);
    }
}

// ---------------------------------------------------------------------------
// Kernel 2: fused sparse contraction + tree evaluation.
// Tile: 64 batch x 32 trees per block (256 threads, 8 warps). Lane owns a
// BATCH PAIR held as float2 -> every uniform decode op feeds 2 FMAs via one
// LDS.64. Sparse-list loads software-pipelined. Response packed as
// float2(r[i], r[i+32]) for LDS.64 epilogue.
// Dynamic smem: 84,224 B.
// ---------------------------------------------------------------------------
#define XS2_OFF   0
#define XS2_SZ    (FEAT * 33 * 8)              // 67584
#define RS2_OFF   (XS2_OFF + XS2_SZ)
#define RS2_SZ    (32 * 32 * 8)                // 8192
#define OUT2_OFF  (RS2_OFF + RS2_SZ)
#define OUT2_SZ   (32 * 33 * 8)                // 8448
#define SMEM_TOT  (OUT2_OFF + OUT2_SZ)         // 84224

__global__ __launch_bounds__(256) void k_forest(
    const float* __restrict__ x,
    const float* __restrict__ response,
    float* __restrict__ out)
{
    extern __shared__ char smem[];
    float2* xs2   = (float2*)(smem + XS2_OFF);   // [f][pair], pitch 33
    float2* rs2   = (float2*)(smem + RS2_OFF);   // [tree][32] = {r[i], r[i+32]}
    float2* outs2 = (float2*)(smem + OUT2_OFF);  // [tree][pair], pitch 33

    const int tid  = threadIdx.x;
    const int lane = tid & 31;
    const int warp = tid >> 5;
    const int b0 = blockIdx.x * 64;
    const int t0 = blockIdx.y * 32;

    // stage x tile: thread = feature tid, gather 32 batch pairs (reads coalesced)
    #pragma unroll 4
    for (int p = 0; p < 32; p++) {
        float lo = x[(b0 + 2 * p    ) * FEAT + tid];
        float hi = x[(b0 + 2 * p + 1) * FEAT + tid];
        xs2[tid * 33 + p] = make_float2(lo, hi);
    }
    // stage response, packed (i, i+32)
    #pragma unroll
    for (int i = tid; i < 32 * 32; i += 256) {
        const int tr = i >> 5, lf = i & 31;
        const float* rr = response + (t0 + tr) * LEAVES;
        rs2[i] = make_float2(rr[lf], rr[lf + 32]);
    }
    __syncthreads();

    for (int tt = warp; tt < 32; tt += 8) {
        const int colb = (t0 + tt) * DEPTH;

        float4 meta[DEPTH];
        #pragma unroll
        for (int dd = 0; dd < DEPTH; dd++) meta[dd] = __ldg(&g_meta[colb + dd]);

        float svl[DEPTH], svh[DEPTH];
        #pragma unroll
        for (int dd = 0; dd < DEPTH; dd++) {
            const int n = __float_as_int(meta[dd].z);       // multiple of 8, >= 8
            const float* __restrict__ wp = g_w + (colb + dd) * NNZ_MAX;
            const unsigned char* __restrict__ ip = g_i + (size_t)(colb + dd) * NNZ_MAX;

            float a0l = 0.f, a0h = 0.f, a1l = 0.f, a1h = 0.f;

            float4 wA = *(const float4*)(wp);
            float4 wB = *(const float4*)(wp + 4);
            uint2  iv = *(const uint2*)(ip);

            #define E2(wv, u, sh, AL, AH) {                                   \
                const int ix = ((u) >> (sh)) & 255;                           \
                const float2 v2 = xs2[ix * 33 + lane];                        \
                AL = fmaf((wv), v2.x, AL); AH = fmaf((wv), v2.y, AH); }

            #define PROC8(WA, WB, IV) {                                       \
                E2(WA.x, IV.x,  0, a0l, a0h); E2(WA.y, IV.x,  8, a1l, a1h);  \
                E2(WA.z, IV.x, 16, a0l, a0h); E2(WA.w, IV.x, 24, a1l, a1h);  \
                E2(WB.x, IV.y,  0, a0l, a0h); E2(WB.y, IV.y,  8, a1l, a1h);  \
                E2(WB.z, IV.y, 16, a0l, a0h); E2(WB.w, IV.y, 24, a1l, a1h); }

            #pragma unroll 1
            for (int j = 8; j < n; j += 8) {
                const float4 nA = *(const float4*)(wp + j);
                const float4 nB = *(const float4*)(wp + j + 4);
                const uint2  niv = *(const uint2*)(ip + j);
                PROC8(wA, wB, iv);
                wA = nA; wB = nB; iv = niv;
            }
            PROC8(wA, wB, iv);
            #undef PROC8
            #undef E2

            const float accl = a0l + a1l;
            const float acch = a0h + a1h;
            svl[dd] = __saturatef(fmaf(0.5f, (accl - meta[dd].x) * meta[dd].y, 0.5f));
            svh[dd] = __saturatef(fmaf(0.5f, (acch - meta[dd].x) * meta[dd].y, 0.5f));
        }

        const float2* __restrict__ r2 = rs2 + tt * 32;
        float2 ov;

        // ---- epilogue, batch-lo ----
        {
            float arr[32];
            arr[0] = 1.0f;
            #pragma unroll
            for (int d = 0; d < 5; d++) {
                const float sd = svl[d], cd = 1.0f - svl[d];
                #pragma unroll
                for (int i = (1 << d) - 1; i >= 0; i--) {
                    float a = arr[i];
                    arr[i + (1 << d)] = a * cd;
                    arr[i]            = a * sd;
                }
            }
            const float s5 = svl[5], c5 = 1.0f - svl[5];
            float o = 0.0f;
            #pragma unroll
            for (int i = 0; i < 32; i++) {
                const float2 q = r2[i];
                o = fmaf(arr[i], fmaf(s5, q.x, c5 * q.y), o);
            }
            ov.x = o;
        }
        // ---- epilogue, batch-hi ----
        {
            float arr[32];
            arr[0] = 1.0f;
            #pragma unroll
            for (int d = 0; d < 5; d++) {
                const float sd = svh[d], cd = 1.0f - svh[d];
                #pragma unroll
                for (int i = (1 << d) - 1; i >= 0; i--) {
                    float a = arr[i];
                    arr[i + (1 << d)] = a * cd;
                    arr[i]            = a * sd;
                }
            }
            const float s5 = svh[5], c5 = 1.0f - svh[5];
            float o = 0.0f;
            #pragma unroll
            for (int i = 0; i < 32; i++) {
                const float2 q = r2[i];
                o = fmaf(arr[i], fmaf(s5, q.x, c5 * q.y), o);
            }
            ov.y = o;
        }
        outs2[tt * 33 + lane] = ov;
    }
    __syncthreads();

    // coalesced store of the 64x32 output tile
    const int tl = tid & 31;             // tree
    const int bg = tid >> 5;             // batch group (8 rows each)
    #pragma unroll
    for (int q = 0; q < 8; q++) {
        const int bb = bg * 8 + q;
        const float2 v = outs2[tl * 33 + (bb >> 1)];
        out[(b0 + bb) * TREES + t0 + tl] = (bb & 1) ? v.y : v.x;
    }
}

// ---------------------------------------------------------------------------
extern "C" void kernel_launch(void* const* d_in, const int* in_sizes, int n_in,
                              void* d_out, int out_size)
{
    const float* x    = (const float*)d_in[0];   // [2048, 256]
    const float* resp = (const float*)d_in[1];   // [256, 1, 64]
    const float* fsl  = (const float*)d_in[2];   // [256, 256, 6]
    const float* th   = (const float*)d_in[3];   // [256, 6]
    const float* lt   = (const float*)d_in[4];   // [256, 6]
    float* out        = (float*)d_out;           // [2048, 256]

    cudaFuncSetAttribute(k_forest, cudaFuncAttributeMaxDynamicSharedMemorySize, SMEM_TOT);

    dim3 gt(NCOLS / 32, FEAT / 32);
    k_transpose<<<gt, dim3(32, 8)>>>(fsl);
    k_sparsemax<<<NCOLS, 256>>>(th, lt);
    dim3 g2(BATCH / 64, TREES / 32);
    k_forest<<<g2, 256, SMEM_TOT>>>(x, resp, out);
}